// round 3
// baseline (speedup 1.0000x reference)
#include <cuda_runtime.h>
#include <math.h>
#include <stdint.h>

#define NN 10000
#define NE 160000
#define HH 8
#define CPD 240
#define EPSLN 1e-5f
#define INV_SQRT2  0.70710678118654752f
#define INV_SQRT3  0.57735026918962576f
#define INV_SQRT32 0.17677669529663689f
#define INV_SQRT48 0.14433756729740643f
#define F_QK0 (1.0f/48.0f)
#define F_QK1 0.018042195912175804f
#define INV16 0.0625f
#define INV_SQRT128 0.08838834764831845f

__device__ float    g_SD[NN*160];
__device__ float    g_QK[(size_t)NN*HH*CPD];
__device__ float    g_LG[NE*HH];
__device__ unsigned g_SMAX[NN*HH];
__device__ float    g_Z[NN*HH];
__device__ __align__(16) float g_MSG[NN*HH*80];

__device__ __forceinline__ unsigned ford(float f) {
    unsigned u = __float_as_uint(f);
    return (u & 0x80000000u) ? ~u : (u | 0x80000000u);
}
__device__ __forceinline__ float finv(unsigned u) {
    return (u & 0x80000000u) ? __uint_as_float(u ^ 0x80000000u) : __uint_as_float(~u);
}
__device__ __forceinline__ float warp_sum(float v) {
    #pragma unroll
    for (int o = 16; o; o >>= 1) v += __shfl_xor_sync(0xffffffffu, v, o);
    return v;
}
__device__ __forceinline__ void fma4(float4& a, float s, const float4 w) {
    a.x = fmaf(s, w.x, a.x); a.y = fmaf(s, w.y, a.y);
    a.z = fmaf(s, w.z, a.z); a.w = fmaf(s, w.w, a.w);
}
__device__ __forceinline__ void red4(float* p, float4 v) {
    asm volatile("red.global.add.v4.f32 [%0], {%1,%2,%3,%4};" ::
                 "l"(p), "f"(v.x), "f"(v.y), "f"(v.z), "f"(v.w) : "memory");
}

__global__ void k_init() {
    int idx = blockIdx.x * blockDim.x + threadIdx.x;
    int stride = gridDim.x * blockDim.x;
    for (int i = idx; i < NN*HH*80; i += stride) g_MSG[i] = 0.0f;
    for (int i = idx; i < NN*HH; i += stride) { g_Z[i] = 0.0f; g_SMAX[i] = 0u; }
}

// per-node: layernorms, s/d projections, QK = q projected through key weights
__global__ void k_node(const float* __restrict__ node,
                       const float* __restrict__ g0, const float* __restrict__ g1,
                       const float* __restrict__ Wq0, const float* __restrict__ Wq1,
                       const float* __restrict__ Ws0, const float* __restrict__ Ws1,
                       const float* __restrict__ Wd0, const float* __restrict__ Wd1,
                       const float* __restrict__ Wkv0, const float* __restrict__ Wkv1) {
    extern __shared__ float sm[];
    float* sW0T = sm;                 // [col<256][c<48]
    float* sW1T = sm + 12288;         // [col<128][u<64]
    int warp = threadIdx.x >> 5, lane = threadIdx.x & 31;
    float* wb  = sm + 12288 + 8192 + warp * 800;
    float* h0s = wb;
    float* h1s = wb + 64;
    float* q0s = wb + 160;
    float* q1s = wb + 416;

    for (int i = threadIdx.x; i < 48*256; i += 256) {
        int c = i >> 8, col = i & 255;
        sW0T[col*48 + c] = Wkv0[c*512 + col];
    }
    for (int i = threadIdx.x; i < 64*128; i += 256) {
        int u = i >> 7, col = i & 127;
        sW1T[col*64 + u] = Wkv1[u*256 + col];
    }
    __syncthreads();

    int n = blockIdx.x * 8 + warp;
    const float* nr = node + (size_t)n * 160;

    float e0 = nr[lane], e1 = nr[32 + lane];
    float mu = warp_sum(e0 + e1) * (1.0f/64.0f);
    float var = warp_sum((e0-mu)*(e0-mu) + (e1-mu)*(e1-mu)) * (1.0f/64.0f);
    float rs0 = rsqrtf(var + EPSLN);
    h0s[lane]    = (e0-mu)*rs0*__ldg(&g0[lane]);
    h0s[32+lane] = (e1-mu)*rs0*__ldg(&g0[32+lane]);
    float t0 = nr[64+lane], t1 = nr[96+lane], t2 = nr[128+lane];
    float vn = warp_sum(t0*t0 + t1*t1 + t2*t2) * (1.0f/32.0f);
    float rs1 = rsqrtf(vn + EPSLN);
    h1s[lane]    = t0*rs1*__ldg(&g1[lane/3]);
    h1s[32+lane] = t1*rs1*__ldg(&g1[(32+lane)/3]);
    h1s[64+lane] = t2*rs1*__ldg(&g1[(64+lane)/3]);
    __syncwarp();

    {   // s0 / d0
        float a = 0.f, b = 0.f;
        #pragma unroll
        for (int i = 0; i < 64; i++) {
            float h = h0s[i];
            a = fmaf(h, __ldg(&Ws0[i*32 + lane]), a);
            b = fmaf(h, __ldg(&Wd0[i*32 + lane]), b);
        }
        g_SD[(size_t)n*160 + lane]      = a * 0.125f;
        g_SD[(size_t)n*160 + 80 + lane] = b * 0.125f;
    }
    #pragma unroll
    for (int rep = 0; rep < 2; rep++) {   // s1 / d1 (48)
        int j = rep*32 + lane;
        if (j < 48) {
            int v_ = j/3, c_ = j%3;
            float a = 0.f, b = 0.f;
            #pragma unroll
            for (int u = 0; u < 32; u++) {
                float h = h1s[u*3 + c_];
                a = fmaf(h, __ldg(&Ws1[u*16 + v_]), a);
                b = fmaf(h, __ldg(&Wd1[u*16 + v_]), b);
            }
            g_SD[(size_t)n*160 + 32 + j]  = a * INV_SQRT32;
            g_SD[(size_t)n*160 + 112 + j] = b * INV_SQRT32;
        }
    }
    #pragma unroll
    for (int h = 0; h < 8; h++) {   // q0
        float a = 0.f;
        #pragma unroll
        for (int i = 0; i < 64; i++) a = fmaf(h0s[i], __ldg(&Wq0[i*256 + h*32 + lane]), a);
        q0s[h*32 + lane] = a * 0.125f;
    }
    #pragma unroll
    for (int k = 0; k < 12; k++) {  // q1 -> q1s[h*48+v*3+c]
        int j = k*32 + lane;
        int h = j/48, r = j%48, v_ = r/3, c_ = r%3;
        float a = 0.f;
        #pragma unroll
        for (int u = 0; u < 32; u++) a = fmaf(h1s[u*3 + c_], __ldg(&Wq1[u*128 + h*16 + v_]), a);
        q1s[j] = a * INV_SQRT32;
    }
    __syncwarp();

    float* qkn = g_QK + (size_t)n * (HH*CPD);
    #pragma unroll
    for (int k = 0; k < 12; k++) {  // qk0 (8x48)
        int j = k*32 + lane;
        int h = j/48, c = j%48;
        float a = 0.f;
        #pragma unroll
        for (int m = 0; m < 32; m++) a = fmaf(q0s[h*32 + m], sW0T[(h*32+m)*48 + c], a);
        qkn[h*CPD + c] = a * F_QK0;
    }
    #pragma unroll
    for (int k = 0; k < 48; k++) {  // qk1 (8x3x64)
        int j = k*32 + lane;
        int h = j/192, cart = (j/64)%3, u = j%64;
        float a = 0.f;
        #pragma unroll
        for (int v_ = 0; v_ < 16; v_++)
            a = fmaf(q1s[h*48 + v_*3 + cart], sW1T[(h*16+v_)*64 + u], a);
        qkn[h*CPD + 48 + cart*64 + u] = a * F_QK1;
    }
}

// build 240-dim tensor-product vector for one edge (warp-cooperative)
__device__ __forceinline__ void build_cp(int e, int src, int dst,
                                         const float* __restrict__ rbf,
                                         const float* __restrict__ rsh,
                                         const float* __restrict__ Ws,
                                         float* wb, float* CP, int lane) {
    float* rb  = wb;
    float* ys  = wb + 16;
    float* x0s = wb + 20;
    float* x1s = wb + 52;
    if (lane < 16) rb[lane] = __ldg(&rbf[(size_t)e*16 + lane]);
    if (lane < 4)  ys[lane] = __ldg(&rsh[(size_t)e*4 + lane]);
    x0s[lane] = __ldg(&g_SD[(size_t)src*160 + lane]) + __ldg(&g_SD[(size_t)dst*160 + 80 + lane]);
    x1s[lane] = __ldg(&g_SD[(size_t)src*160 + 32 + lane]) + __ldg(&g_SD[(size_t)dst*160 + 112 + lane]);
    if (lane < 16)
        x1s[32+lane] = __ldg(&g_SD[(size_t)src*160 + 64 + lane]) + __ldg(&g_SD[(size_t)dst*160 + 144 + lane]);
    __syncwarp();

    float y0 = ys[0], y1x = ys[1], y1y = ys[2], y1z = ys[3];
    #define WCH(J, OUT) { float _a = 0.f; _Pragma("unroll") \
        for (int _k = 0; _k < 16; _k++) _a = fmaf(rb[_k], Ws[_k*112 + (J)], _a); OUT = _a; }

    { float w; WCH(lane, w); CP[lane] = w * x0s[lane] * y0; }
    if (lane < 16) {
        float w; WCH(32 + lane, w);
        float d = x1s[lane*3]*y1x + x1s[lane*3+1]*y1y + x1s[lane*3+2]*y1z;
        CP[32 + lane] = w * d * INV_SQRT3;
    }
    { float w; WCH(48 + lane, w);
      float xv = w * x0s[lane];
      CP[48 + lane]       = xv * y1x;
      CP[48 + 64 + lane]  = xv * y1y;
      CP[48 + 128 + lane] = xv * y1z; }
    if (lane < 16) {
        float w; WCH(80 + lane, w);
        float wy = w * y0;
        CP[48 + 32 + lane]       = wy * x1s[lane*3];
        CP[48 + 64 + 32 + lane]  = wy * x1s[lane*3+1];
        CP[48 + 128 + 32 + lane] = wy * x1s[lane*3+2];
    } else {
        int t = lane - 16;
        float w; WCH(96 + t, w);
        w *= INV_SQRT2;
        float ax = x1s[t*3], ay = x1s[t*3+1], az = x1s[t*3+2];
        CP[48 + 48 + t]       = w * (ay*y1z - az*y1y);
        CP[48 + 64 + 48 + t]  = w * (az*y1x - ax*y1z);
        CP[48 + 128 + 48 + t] = w * (ax*y1y - ay*y1x);
    }
    #undef WCH
    __syncwarp();
}

__global__ void k_logits(const float* __restrict__ rbf, const float* __restrict__ rsh,
                         const int* __restrict__ ei, const float* __restrict__ Wrbf) {
    __shared__ float sW[16*112];
    __shared__ float wbuf[8][344];
    int warp = threadIdx.x >> 5, lane = threadIdx.x & 31;
    for (int i = threadIdx.x; i < 16*112; i += 256) sW[i] = Wrbf[i];
    __syncthreads();

    int e = blockIdx.x * 8 + warp;
    int src = __ldg(&ei[e]), dst = __ldg(&ei[NE + e]);
    float* wb = wbuf[warp];
    float* CP = wb + 100;
    build_cp(e, src, dst, rbf, rsh, sW, wb, CP, lane);

    const float* qkb = g_QK + (size_t)src * (HH*CPD);
    #pragma unroll
    for (int h = 0; h < 8; h++) {
        const float* qk = qkb + h*CPD;
        float a = 0.f;
        for (int j = lane; j < CPD; j += 32) a = fmaf(CP[j], __ldg(&qk[j]), a);
        a = warp_sum(a);
        if (lane == 0) {
            g_LG[(size_t)e*8 + h] = a;
            atomicMax(&g_SMAX[dst*8 + h], ford(a));
        }
    }
}

__global__ void k_expz(const int* __restrict__ ei) {
    int idx = blockIdx.x * blockDim.x + threadIdx.x;
    int e = idx >> 3, h = idx & 7;
    int dst = __ldg(&ei[NE + e]);
    float m = finv(g_SMAX[dst*8 + h]);
    float a = expf(g_LG[idx] - m);
    g_LG[idx] = a;
    atomicAdd(&g_Z[dst*8 + h], a);
}

// value GEMM + attention-weighted scatter, 4 edges per warp
__global__ void k_val(const float* __restrict__ rbf, const float* __restrict__ rsh,
                      const int* __restrict__ ei, const float* __restrict__ Wrbf,
                      const float* __restrict__ Wkv0, const float* __restrict__ Wkv1) {
    __shared__ float sW[16*112];
    __shared__ float wbuf[8][1072];
    int warp = threadIdx.x >> 5, lane = threadIdx.x & 31;
    for (int i = threadIdx.x; i < 16*112; i += 256) sW[i] = Wrbf[i];
    __syncthreads();

    int e0 = (blockIdx.x * 8 + warp) * 4;
    float* wb = wbuf[warp];
    float* CP = wb + 100;

    int h  = lane >> 2;
    int mb = (lane & 3) * 8;
    int vb = (lane & 3) * 4;

    int dq[4];
    float attnq[4];
    #pragma unroll
    for (int q = 0; q < 4; q++) {
        int e = e0 + q;
        int src = __ldg(&ei[e]);
        int dst = __ldg(&ei[NE + e]);
        dq[q] = dst;
        build_cp(e, src, dst, rbf, rsh, sW, wb, CP + q*CPD, lane);
        attnq[q] = __ldg(&g_LG[(size_t)e*8 + h]) / (__ldg(&g_Z[dst*8 + h]) + 1e-16f);
    }

    {   // scalar values: this lane covers m = mb..mb+7 of head h
        float4 acc[4][2];
        #pragma unroll
        for (int q = 0; q < 4; q++) { acc[q][0] = make_float4(0,0,0,0); acc[q][1] = make_float4(0,0,0,0); }
        const float* W0 = Wkv0 + 256 + h*32 + mb;
        #pragma unroll 4
        for (int c = 0; c < 48; c++) {
            float4 wa = __ldg((const float4*)(W0 + c*512));
            float4 wc = __ldg((const float4*)(W0 + c*512 + 4));
            #pragma unroll
            for (int q = 0; q < 4; q++) {
                float cp = CP[q*CPD + c];
                fma4(acc[q][0], cp, wa);
                fma4(acc[q][1], cp, wc);
            }
        }
        #pragma unroll
        for (int q = 0; q < 4; q++) {
            float f = attnq[q] * INV_SQRT48;
            float* dp = g_MSG + (size_t)dq[q]*640 + h*80 + mb;
            red4(dp,     make_float4(acc[q][0].x*f, acc[q][0].y*f, acc[q][0].z*f, acc[q][0].w*f));
            red4(dp + 4, make_float4(acc[q][1].x*f, acc[q][1].y*f, acc[q][1].z*f, acc[q][1].w*f));
        }
    }
    {   // vector values: this lane covers v = vb..vb+3 of head h
        float4 a1[4][3];
        #pragma unroll
        for (int q = 0; q < 4; q++)
            #pragma unroll
            for (int c = 0; c < 3; c++) a1[q][c] = make_float4(0,0,0,0);
        const float* W1 = Wkv1 + 128 + h*16 + vb;
        #pragma unroll 4
        for (int u = 0; u < 64; u++) {
            float4 w = __ldg((const float4*)(W1 + u*256));
            #pragma unroll
            for (int q = 0; q < 4; q++)
                #pragma unroll
                for (int c = 0; c < 3; c++)
                    fma4(a1[q][c], CP[q*CPD + 48 + c*64 + u], w);
        }
        #pragma unroll
        for (int q = 0; q < 4; q++) {
            float f = attnq[q] * 0.125f;
            float* dp = g_MSG + (size_t)dq[q]*640 + h*80 + 32 + vb*3;
            red4(dp,     make_float4(a1[q][0].x*f, a1[q][1].x*f, a1[q][2].x*f, a1[q][0].y*f));
            red4(dp + 4, make_float4(a1[q][1].y*f, a1[q][2].y*f, a1[q][0].z*f, a1[q][1].z*f));
            red4(dp + 8, make_float4(a1[q][2].z*f, a1[q][0].w*f, a1[q][1].w*f, a1[q][2].w*f));
        }
    }
}

__global__ void k_out(const float* __restrict__ node,
                      const float* __restrict__ Wm0, const float* __restrict__ Wm1,
                      float* __restrict__ out) {
    __shared__ float msgs_all[8][640];
    int warp = threadIdx.x >> 5, lane = threadIdx.x & 31;
    int n = blockIdx.x * 8 + warp;
    float* msgs = msgs_all[warp];
    for (int j = lane; j < 640; j += 32) msgs[j] = g_MSG[(size_t)n*640 + j];
    __syncwarp();

    const float* nr = node + (size_t)n * 160;
    float* orow = out + (size_t)n * 160;

    float a0 = 0.f, a1 = 0.f;
    #pragma unroll 8
    for (int i = 0; i < 256; i++) {
        float m = msgs[(i >> 5)*80 + (i & 31)];
        a0 = fmaf(m, __ldg(&Wm0[i*64 + lane]), a0);
        a1 = fmaf(m, __ldg(&Wm0[i*64 + 32 + lane]), a1);
    }
    orow[lane]      = nr[lane]      + a0 * INV16;
    orow[32 + lane] = nr[32 + lane] + a1 * INV16;

    float c0 = 0.f, c1 = 0.f, c2 = 0.f;
    #pragma unroll 8
    for (int u = 0; u < 128; u++) {
        int hh = u >> 4, v_ = u & 15;
        float w = __ldg(&Wm1[u*32 + lane]);
        const float* mp = msgs + hh*80 + 32 + v_*3;
        c0 = fmaf(mp[0], w, c0);
        c1 = fmaf(mp[1], w, c1);
        c2 = fmaf(mp[2], w, c2);
    }
    orow[64 + lane*3 + 0] = nr[64 + lane*3 + 0] + c0 * INV_SQRT128;
    orow[64 + lane*3 + 1] = nr[64 + lane*3 + 1] + c1 * INV_SQRT128;
    orow[64 + lane*3 + 2] = nr[64 + lane*3 + 2] + c2 * INV_SQRT128;
}

extern "C" void kernel_launch(void* const* d_in, const int* in_sizes, int n_in,
                              void* d_out, int out_size) {
    const float* node = (const float*)d_in[0];
    const float* rbf  = (const float*)d_in[1];
    const float* rsh  = (const float*)d_in[2];
    const int*   ei   = (const int*)d_in[3];
    const float* g0   = (const float*)d_in[4];
    const float* g1   = (const float*)d_in[5];
    const float* Wq0  = (const float*)d_in[6];
    const float* Wq1  = (const float*)d_in[7];
    const float* Ws0  = (const float*)d_in[8];
    const float* Ws1  = (const float*)d_in[9];
    const float* Wd0  = (const float*)d_in[10];
    const float* Wd1  = (const float*)d_in[11];
    const float* Wrbf = (const float*)d_in[12];
    const float* Wkv0 = (const float*)d_in[13];
    const float* Wkv1 = (const float*)d_in[14];
    const float* Wm0  = (const float*)d_in[15];
    const float* Wm1  = (const float*)d_in[16];
    float* out = (float*)d_out;

    static int smem_set = 0;
    if (!smem_set) {
        cudaFuncSetAttribute(k_node, cudaFuncAttributeMaxDynamicSharedMemorySize, 107520);
        smem_set = 1;
    }

    k_init<<<512, 256>>>();
    k_node<<<NN/8, 256, 107520>>>(node, g0, g1, Wq0, Wq1, Ws0, Ws1, Wd0, Wd1, Wkv0, Wkv1);
    k_logits<<<NE/8, 256>>>(rbf, rsh, ei, Wrbf);
    k_expz<<<(NE*8)/256, 256>>>(ei);
    k_val<<<NE/32, 256>>>(rbf, rsh, ei, Wrbf, Wkv0, Wkv1);
    k_out<<<NN/8, 256>>>(node, Wm0, Wm1, out);
}

// round 4
// speedup vs baseline: 1.2608x; 1.2608x over previous
#include <cuda_runtime.h>
#include <math.h>
#include <stdint.h>

#define NN 10000
#define NE 160000
#define HH 8
#define CPD 240
#define EPSLN 1e-5f
#define INV_SQRT2  0.70710678118654752f
#define INV_SQRT3  0.57735026918962576f
#define INV_SQRT32 0.17677669529663689f
#define INV_SQRT48 0.14433756729740643f
#define F_QK0 (1.0f/48.0f)
#define F_QK1 0.018042195912175804f
#define INV16 0.0625f
#define INV_SQRT128 0.08838834764831845f

__device__ float g_SD[NN*160];
__device__ float g_QK[(size_t)NN*HH*CPD];
__device__ __align__(16) float g_CP[(size_t)NE*256];
__device__ float g_LG[(size_t)NE*8];
__device__ int   g_CNT[NN];
__device__ int   g_OFF[NN+1];
__device__ int   g_CUR[NN];
__device__ int   g_EID[NE];
__device__ __align__(16) float g_MSG[NN*640];

__device__ __forceinline__ float warp_sum(float v) {
    #pragma unroll
    for (int o = 16; o; o >>= 1) v += __shfl_xor_sync(0xffffffffu, v, o);
    return v;
}
__device__ __forceinline__ void fma4(float4& a, float s, const float4 w) {
    a.x = fmaf(s, w.x, a.x); a.y = fmaf(s, w.y, a.y);
    a.z = fmaf(s, w.z, a.z); a.w = fmaf(s, w.w, a.w);
}

__global__ void k_init() {
    int i = blockIdx.x * blockDim.x + threadIdx.x;
    if (i < NN) g_CNT[i] = 0;
}

// per-node: layernorms, s/d projections, QK = q projected through key weights
__global__ void k_node(const float* __restrict__ node,
                       const float* __restrict__ g0, const float* __restrict__ g1,
                       const float* __restrict__ Wq0, const float* __restrict__ Wq1,
                       const float* __restrict__ Ws0, const float* __restrict__ Ws1,
                       const float* __restrict__ Wd0, const float* __restrict__ Wd1,
                       const float* __restrict__ Wkv0, const float* __restrict__ Wkv1) {
    extern __shared__ float sm[];
    float* sW0T = sm;                 // [col<256][c<48]
    float* sW1T = sm + 12288;         // [col<128][u<64]
    int warp = threadIdx.x >> 5, lane = threadIdx.x & 31;
    float* wb  = sm + 12288 + 8192 + warp * 800;
    float* h0s = wb;
    float* h1s = wb + 64;
    float* q0s = wb + 160;
    float* q1s = wb + 416;

    for (int i = threadIdx.x; i < 48*256; i += 256) {
        int c = i >> 8, col = i & 255;
        sW0T[col*48 + c] = Wkv0[c*512 + col];
    }
    for (int i = threadIdx.x; i < 64*128; i += 256) {
        int u = i >> 7, col = i & 127;
        sW1T[col*64 + u] = Wkv1[u*256 + col];
    }
    __syncthreads();

    int n = blockIdx.x * 8 + warp;
    const float* nr = node + (size_t)n * 160;

    float e0 = nr[lane], e1 = nr[32 + lane];
    float mu = warp_sum(e0 + e1) * (1.0f/64.0f);
    float var = warp_sum((e0-mu)*(e0-mu) + (e1-mu)*(e1-mu)) * (1.0f/64.0f);
    float rs0 = rsqrtf(var + EPSLN);
    h0s[lane]    = (e0-mu)*rs0*__ldg(&g0[lane]);
    h0s[32+lane] = (e1-mu)*rs0*__ldg(&g0[32+lane]);
    float t0 = nr[64+lane], t1 = nr[96+lane], t2 = nr[128+lane];
    float vn = warp_sum(t0*t0 + t1*t1 + t2*t2) * (1.0f/32.0f);
    float rs1 = rsqrtf(vn + EPSLN);
    h1s[lane]    = t0*rs1*__ldg(&g1[lane/3]);
    h1s[32+lane] = t1*rs1*__ldg(&g1[(32+lane)/3]);
    h1s[64+lane] = t2*rs1*__ldg(&g1[(64+lane)/3]);
    __syncwarp();

    {
        float a = 0.f, b = 0.f;
        #pragma unroll
        for (int i = 0; i < 64; i++) {
            float h = h0s[i];
            a = fmaf(h, __ldg(&Ws0[i*32 + lane]), a);
            b = fmaf(h, __ldg(&Wd0[i*32 + lane]), b);
        }
        g_SD[(size_t)n*160 + lane]      = a * 0.125f;
        g_SD[(size_t)n*160 + 80 + lane] = b * 0.125f;
    }
    #pragma unroll
    for (int rep = 0; rep < 2; rep++) {
        int j = rep*32 + lane;
        if (j < 48) {
            int v_ = j/3, c_ = j%3;
            float a = 0.f, b = 0.f;
            #pragma unroll
            for (int u = 0; u < 32; u++) {
                float h = h1s[u*3 + c_];
                a = fmaf(h, __ldg(&Ws1[u*16 + v_]), a);
                b = fmaf(h, __ldg(&Wd1[u*16 + v_]), b);
            }
            g_SD[(size_t)n*160 + 32 + j]  = a * INV_SQRT32;
            g_SD[(size_t)n*160 + 112 + j] = b * INV_SQRT32;
        }
    }
    #pragma unroll
    for (int h = 0; h < 8; h++) {
        float a = 0.f;
        #pragma unroll
        for (int i = 0; i < 64; i++) a = fmaf(h0s[i], __ldg(&Wq0[i*256 + h*32 + lane]), a);
        q0s[h*32 + lane] = a * 0.125f;
    }
    #pragma unroll
    for (int k = 0; k < 12; k++) {
        int j = k*32 + lane;
        int h = j/48, r = j%48, v_ = r/3, c_ = r%3;
        float a = 0.f;
        #pragma unroll
        for (int u = 0; u < 32; u++) a = fmaf(h1s[u*3 + c_], __ldg(&Wq1[u*128 + h*16 + v_]), a);
        q1s[j] = a * INV_SQRT32;
    }
    __syncwarp();

    float* qkn = g_QK + (size_t)n * (HH*CPD);
    #pragma unroll
    for (int k = 0; k < 12; k++) {
        int j = k*32 + lane;
        int h = j/48, c = j%48;
        float a = 0.f;
        #pragma unroll
        for (int m = 0; m < 32; m++) a = fmaf(q0s[h*32 + m], sW0T[(h*32+m)*48 + c], a);
        qkn[h*CPD + c] = a * F_QK0;
    }
    #pragma unroll
    for (int k = 0; k < 48; k++) {
        int j = k*32 + lane;
        int h = j/192, cart = (j/64)%3, u = j%64;
        float a = 0.f;
        #pragma unroll
        for (int v_ = 0; v_ < 16; v_++)
            a = fmaf(q1s[h*48 + v_*3 + cart], sW1T[(h*16+v_)*64 + u], a);
        qkn[h*CPD + 48 + cart*64 + u] = a * F_QK1;
    }
}

// build 240-dim tensor-product vector for one edge (warp-cooperative)
__device__ __forceinline__ void build_cp(int e, int src, int dst,
                                         const float* __restrict__ rbf,
                                         const float* __restrict__ rsh,
                                         const float* __restrict__ Ws,
                                         float* wb, float* CP, int lane) {
    float* rb  = wb;
    float* ys  = wb + 16;
    float* x0s = wb + 20;
    float* x1s = wb + 52;
    if (lane < 16) rb[lane] = __ldg(&rbf[(size_t)e*16 + lane]);
    if (lane < 4)  ys[lane] = __ldg(&rsh[(size_t)e*4 + lane]);
    x0s[lane] = __ldg(&g_SD[(size_t)src*160 + lane]) + __ldg(&g_SD[(size_t)dst*160 + 80 + lane]);
    x1s[lane] = __ldg(&g_SD[(size_t)src*160 + 32 + lane]) + __ldg(&g_SD[(size_t)dst*160 + 112 + lane]);
    if (lane < 16)
        x1s[32+lane] = __ldg(&g_SD[(size_t)src*160 + 64 + lane]) + __ldg(&g_SD[(size_t)dst*160 + 144 + lane]);
    __syncwarp();

    float y0 = ys[0], y1x = ys[1], y1y = ys[2], y1z = ys[3];
    #define WCH(J, OUT) { float _a = 0.f; _Pragma("unroll") \
        for (int _k = 0; _k < 16; _k++) _a = fmaf(rb[_k], Ws[_k*112 + (J)], _a); OUT = _a; }

    { float w; WCH(lane, w); CP[lane] = w * x0s[lane] * y0; }
    if (lane < 16) {
        float w; WCH(32 + lane, w);
        float d = x1s[lane*3]*y1x + x1s[lane*3+1]*y1y + x1s[lane*3+2]*y1z;
        CP[32 + lane] = w * d * INV_SQRT3;
    }
    { float w; WCH(48 + lane, w);
      float xv = w * x0s[lane];
      CP[48 + lane]       = xv * y1x;
      CP[48 + 64 + lane]  = xv * y1y;
      CP[48 + 128 + lane] = xv * y1z; }
    if (lane < 16) {
        float w; WCH(80 + lane, w);
        float wy = w * y0;
        CP[48 + 32 + lane]       = wy * x1s[lane*3];
        CP[48 + 64 + 32 + lane]  = wy * x1s[lane*3+1];
        CP[48 + 128 + 32 + lane] = wy * x1s[lane*3+2];
    } else {
        int t = lane - 16;
        float w; WCH(96 + t, w);
        w *= INV_SQRT2;
        float ax = x1s[t*3], ay = x1s[t*3+1], az = x1s[t*3+2];
        CP[48 + 48 + t]       = w * (ay*y1z - az*y1y);
        CP[48 + 64 + 48 + t]  = w * (az*y1x - ax*y1z);
        CP[48 + 128 + 48 + t] = w * (ax*y1y - ay*y1x);
    }
    #undef WCH
    __syncwarp();
}

// per-edge: build+store CP, logits, dst histogram
__global__ void k_edge(const float* __restrict__ rbf, const float* __restrict__ rsh,
                       const int* __restrict__ ei, const float* __restrict__ Wrbf) {
    __shared__ float sW[16*112];
    __shared__ __align__(16) float wbuf[8][352];
    int warp = threadIdx.x >> 5, lane = threadIdx.x & 31;
    for (int i = threadIdx.x; i < 16*112; i += 256) sW[i] = Wrbf[i];
    __syncthreads();

    int e = blockIdx.x * 8 + warp;
    int src = __ldg(&ei[e]), dst = __ldg(&ei[NE + e]);
    float* wb = wbuf[warp];
    float* CP = wb + 112;     // 16B-aligned
    build_cp(e, src, dst, rbf, rsh, sW, wb, CP, lane);

    // store CP to global (padded row of 256 floats)
    float4* dcp = (float4*)(g_CP + (size_t)e*256);
    const float4* scp = (const float4*)CP;
    dcp[lane] = scp[lane];
    if (lane < 28) dcp[32+lane] = scp[32+lane];

    // logits for all 8 heads
    float acc[8] = {0,0,0,0,0,0,0,0};
    const float* qkb = g_QK + (size_t)src * 1920;
    for (int j = lane; j < 240; j += 32) {
        float cp = CP[j];
        #pragma unroll
        for (int h = 0; h < 8; h++) acc[h] = fmaf(cp, __ldg(&qkb[h*240 + j]), acc[h]);
    }
    #pragma unroll
    for (int o = 16; o; o >>= 1)
        #pragma unroll
        for (int h = 0; h < 8; h++) acc[h] += __shfl_xor_sync(0xffffffffu, acc[h], o);
    if (lane < 8) g_LG[(size_t)e*8 + lane] = acc[lane];
    if (lane == 0) atomicAdd(&g_CNT[dst], 1);
}

// exclusive prefix scan of counts (single block)
__global__ void k_scan() {
    __shared__ int ssum[512];
    int t = threadIdx.x;
    int base = t * 20;
    int loc[20];
    int s = 0;
    #pragma unroll
    for (int i = 0; i < 20; i++) {
        int idx = base + i;
        int c = (idx < NN) ? g_CNT[idx] : 0;
        loc[i] = s; s += c;
    }
    ssum[t] = s;
    __syncthreads();
    for (int off = 1; off < 512; off <<= 1) {
        int v = (t >= off) ? ssum[t - off] : 0;
        __syncthreads();
        ssum[t] += v;
        __syncthreads();
    }
    int excl = ssum[t] - s;
    #pragma unroll
    for (int i = 0; i < 20; i++) {
        int idx = base + i;
        if (idx < NN) { int o = excl + loc[i]; g_OFF[idx] = o; g_CUR[idx] = o; }
    }
    if (t == 511) g_OFF[NN] = ssum[511];
}

__global__ void k_bucket(const int* __restrict__ ei) {
    int e = blockIdx.x * 256 + threadIdx.x;
    int dst = __ldg(&ei[NE + e]);
    int pos = atomicAdd(&g_CUR[dst], 1);
    g_EID[pos] = e;
}

// per-node: softmax over its in-edges, accumulate attn-weighted CP, value GEMM
__global__ void k_gather(const float* __restrict__ Wkv0, const float* __restrict__ Wkv1) {
    extern __shared__ float sg[];
    float* sWv0 = sg;             // [c<48][j<256]  value half of Wkv0
    float* sWv1 = sg + 12288;     // [u<64][j<128]  value half of Wkv1
    float* sACP = sg + 20480;     // 8 warps x 2048
    float* sMZ  = sg + 36864;     // 8 warps x 16

    int warp = threadIdx.x >> 5, lane = threadIdx.x & 31;
    for (int i = threadIdx.x; i < 12288; i += 256) {
        int c = i >> 8, j = i & 255;
        sWv0[i] = Wkv0[c*512 + 256 + j];
    }
    for (int i = threadIdx.x; i < 8192; i += 256) {
        int u = i >> 7, j = i & 127;
        sWv1[i] = Wkv1[u*256 + 128 + j];
    }
    __syncthreads();

    int n = blockIdx.x * 8 + warp;
    int start = g_OFF[n];
    int deg = g_OFF[n+1] - start;

    // pass 1: per-head max and Z  (lane = q*8 + h)
    int q = lane >> 3, h = lane & 7;
    float m = -INFINITY;
    for (int i = q; i < deg; i += 4) {
        int e = g_EID[start + i];
        m = fmaxf(m, __ldg(&g_LG[(size_t)e*8 + h]));
    }
    m = fmaxf(m, __shfl_xor_sync(0xffffffffu, m, 8));
    m = fmaxf(m, __shfl_xor_sync(0xffffffffu, m, 16));
    float z = 0.f;
    for (int i = q; i < deg; i += 4) {
        int e = g_EID[start + i];
        z += expf(__ldg(&g_LG[(size_t)e*8 + h]) - m);
    }
    z += __shfl_xor_sync(0xffffffffu, z, 8);
    z += __shfl_xor_sync(0xffffffffu, z, 16);
    float* mz = sMZ + warp*16;
    if (lane < 8) { mz[lane] = m; mz[8 + lane] = 1.f / (z + 1e-16f); }
    __syncwarp();

    // pass 2: accumulate attn-weighted CP in registers
    float4 aA[8], aB[8];
    #pragma unroll
    for (int hh = 0; hh < 8; hh++) { aA[hh] = make_float4(0,0,0,0); aB[hh] = make_float4(0,0,0,0); }
    for (int i = 0; i < deg; i++) {
        int e = g_EID[start + i];
        float att = 0.f;
        if (lane < 8)
            att = expf(__ldg(&g_LG[(size_t)e*8 + lane]) - mz[lane]) * mz[8 + lane];
        const float4* cp4 = (const float4*)(g_CP + (size_t)e*256);
        float4 c4a = __ldg(&cp4[lane]);
        float4 c4b = (lane < 28) ? __ldg(&cp4[32 + lane]) : make_float4(0,0,0,0);
        #pragma unroll
        for (int hh = 0; hh < 8; hh++) {
            float a = __shfl_sync(0xffffffffu, att, hh);
            fma4(aA[hh], a, c4a);
            fma4(aB[hh], a, c4b);
        }
    }
    float* sa = sACP + warp*2048;
    #pragma unroll
    for (int hh = 0; hh < 8; hh++) {
        ((float4*)sa)[hh*64 + lane] = aA[hh];
        ((float4*)sa)[hh*64 + 32 + lane] = aB[hh];
    }
    __syncwarp();

    // value GEMM: msg0[h][m], m = lane
    float acc0[8] = {0,0,0,0,0,0,0,0};
    for (int c = 0; c < 48; c += 4) {
        #pragma unroll
        for (int hh = 0; hh < 8; hh++) {
            float4 a4 = *(const float4*)(sa + hh*256 + c);
            float r = acc0[hh];
            r = fmaf(a4.x, sWv0[(c+0)*256 + hh*32 + lane], r);
            r = fmaf(a4.y, sWv0[(c+1)*256 + hh*32 + lane], r);
            r = fmaf(a4.z, sWv0[(c+2)*256 + hh*32 + lane], r);
            r = fmaf(a4.w, sWv0[(c+3)*256 + hh*32 + lane], r);
            acc0[hh] = r;
        }
    }
    float* mrow = g_MSG + (size_t)n * 640;
    #pragma unroll
    for (int hh = 0; hh < 8; hh++) mrow[hh*80 + lane] = acc0[hh] * INV_SQRT48;

    // msg1: outputs j = lane + 32k (h = j>>4, v = j&15), 3 cartesian comps
    float acc1[4][3];
    #pragma unroll
    for (int k = 0; k < 4; k++)
        #pragma unroll
        for (int c = 0; c < 3; c++) acc1[k][c] = 0.f;
    for (int u = 0; u < 64; u += 4) {
        #pragma unroll
        for (int k = 0; k < 4; k++) {
            int jj = lane + 32*k;
            int hb = jj >> 4;
            const float* ap = sa + hb*256 + 48 + u;
            float4 ax = *(const float4*)(ap);
            float4 ay = *(const float4*)(ap + 64);
            float4 az = *(const float4*)(ap + 128);
            float w0 = sWv1[(u+0)*128 + jj];
            float w1 = sWv1[(u+1)*128 + jj];
            float w2 = sWv1[(u+2)*128 + jj];
            float w3 = sWv1[(u+3)*128 + jj];
            acc1[k][0] = fmaf(ax.x,w0, fmaf(ax.y,w1, fmaf(ax.z,w2, fmaf(ax.w,w3, acc1[k][0]))));
            acc1[k][1] = fmaf(ay.x,w0, fmaf(ay.y,w1, fmaf(ay.z,w2, fmaf(ay.w,w3, acc1[k][1]))));
            acc1[k][2] = fmaf(az.x,w0, fmaf(az.y,w1, fmaf(az.z,w2, fmaf(az.w,w3, acc1[k][2]))));
        }
    }
    #pragma unroll
    for (int k = 0; k < 4; k++) {
        int jj = lane + 32*k;
        int hb = jj >> 4, v_ = jj & 15;
        #pragma unroll
        for (int c = 0; c < 3; c++)
            mrow[hb*80 + 32 + v_*3 + c] = acc1[k][c] * 0.125f;
    }
}

__global__ void k_out(const float* __restrict__ node,
                      const float* __restrict__ Wm0, const float* __restrict__ Wm1,
                      float* __restrict__ out) {
    __shared__ float msgs_all[8][640];
    int warp = threadIdx.x >> 5, lane = threadIdx.x & 31;
    int n = blockIdx.x * 8 + warp;
    float* msgs = msgs_all[warp];
    for (int j = lane; j < 640; j += 32) msgs[j] = g_MSG[(size_t)n*640 + j];
    __syncwarp();

    const float* nr = node + (size_t)n * 160;
    float* orow = out + (size_t)n * 160;

    float a0 = 0.f, a1 = 0.f;
    #pragma unroll 8
    for (int i = 0; i < 256; i++) {
        float m = msgs[(i >> 5)*80 + (i & 31)];
        a0 = fmaf(m, __ldg(&Wm0[i*64 + lane]), a0);
        a1 = fmaf(m, __ldg(&Wm0[i*64 + 32 + lane]), a1);
    }
    orow[lane]      = nr[lane]      + a0 * INV16;
    orow[32 + lane] = nr[32 + lane] + a1 * INV16;

    float c0 = 0.f, c1 = 0.f, c2 = 0.f;
    #pragma unroll 8
    for (int u = 0; u < 128; u++) {
        int hh = u >> 4, v_ = u & 15;
        float w = __ldg(&Wm1[u*32 + lane]);
        const float* mp = msgs + hh*80 + 32 + v_*3;
        c0 = fmaf(mp[0], w, c0);
        c1 = fmaf(mp[1], w, c1);
        c2 = fmaf(mp[2], w, c2);
    }
    orow[64 + lane*3 + 0] = nr[64 + lane*3 + 0] + c0 * INV_SQRT128;
    orow[64 + lane*3 + 1] = nr[64 + lane*3 + 1] + c1 * INV_SQRT128;
    orow[64 + lane*3 + 2] = nr[64 + lane*3 + 2] + c2 * INV_SQRT128;
}

extern "C" void kernel_launch(void* const* d_in, const int* in_sizes, int n_in,
                              void* d_out, int out_size) {
    const float* node = (const float*)d_in[0];
    const float* rbf  = (const float*)d_in[1];
    const float* rsh  = (const float*)d_in[2];
    const int*   ei   = (const int*)d_in[3];
    const float* g0   = (const float*)d_in[4];
    const float* g1   = (const float*)d_in[5];
    const float* Wq0  = (const float*)d_in[6];
    const float* Wq1  = (const float*)d_in[7];
    const float* Ws0  = (const float*)d_in[8];
    const float* Ws1  = (const float*)d_in[9];
    const float* Wd0  = (const float*)d_in[10];
    const float* Wd1  = (const float*)d_in[11];
    const float* Wrbf = (const float*)d_in[12];
    const float* Wkv0 = (const float*)d_in[13];
    const float* Wkv1 = (const float*)d_in[14];
    const float* Wm0  = (const float*)d_in[15];
    const float* Wm1  = (const float*)d_in[16];
    float* out = (float*)d_out;

    cudaFuncSetAttribute(k_node, cudaFuncAttributeMaxDynamicSharedMemorySize, 107520);
    cudaFuncSetAttribute(k_gather, cudaFuncAttributeMaxDynamicSharedMemorySize, 147968);

    k_init<<<40, 256>>>();
    k_node<<<NN/8, 256, 107520>>>(node, g0, g1, Wq0, Wq1, Ws0, Ws1, Wd0, Wd1, Wkv0, Wkv1);
    k_edge<<<NE/8, 256>>>(rbf, rsh, ei, Wrbf);
    k_scan<<<1, 512>>>();
    k_bucket<<<NE/256, 256>>>(ei);
    k_gather<<<NN/8, 256, 147968>>>(Wkv0, Wkv1);
    k_out<<<NN/8, 256>>>(node, Wm0, Wm1, out);
}

// round 5
// speedup vs baseline: 1.2839x; 1.0183x over previous
#include <cuda_runtime.h>
#include <math.h>
#include <stdint.h>

#define NN 10000
#define NE 160000
#define HH 8
#define CPD 240
#define EPSLN 1e-5f
#define INV_SQRT2  0.70710678118654752f
#define INV_SQRT3  0.57735026918962576f
#define INV_SQRT32 0.17677669529663689f
#define INV_SQRT48 0.14433756729740643f
#define F_QK0 (1.0f/48.0f)
#define F_QK1 0.018042195912175804f
#define INV16 0.0625f
#define INV_SQRT128 0.08838834764831845f

__device__ float g_SD[NN*160];
__device__ __align__(16) float g_QK[(size_t)NN*HH*CPD];   // layout [n][j<240][h<8]
__device__ __align__(16) float g_CP[(size_t)NE*256];
__device__ float g_LG[(size_t)NE*8];
__device__ int   g_CNTS[NN], g_CNTD[NN];
__device__ int   g_OFFS[NN+1], g_OFFD[NN+1];
__device__ int   g_CURS[NN], g_CURD[NN];
__device__ int   g_SEID[NE], g_DEID[NE];
__device__ __align__(16) float g_MSG[NN*640];

__device__ __forceinline__ float warp_sum(float v) {
    #pragma unroll
    for (int o = 16; o; o >>= 1) v += __shfl_xor_sync(0xffffffffu, v, o);
    return v;
}
__device__ __forceinline__ void fma4(float4& a, float s, const float4 w) {
    a.x = fmaf(s, w.x, a.x); a.y = fmaf(s, w.y, a.y);
    a.z = fmaf(s, w.z, a.z); a.w = fmaf(s, w.w, a.w);
}

__global__ void k_init() {
    int i = blockIdx.x * blockDim.x + threadIdx.x;
    if (i < NN) { g_CNTS[i] = 0; g_CNTD[i] = 0; }
}

__global__ void k_hist(const int* __restrict__ ei) {
    int e = blockIdx.x * 256 + threadIdx.x;
    atomicAdd(&g_CNTS[__ldg(&ei[e])], 1);
    atomicAdd(&g_CNTD[__ldg(&ei[NE + e])], 1);
}

// shuffle-based exclusive scan; blockIdx 0 -> src, 1 -> dst
__global__ void k_scan() {
    __shared__ int swt[16], swe[16];
    const int* cnt = (blockIdx.x == 0) ? g_CNTS : g_CNTD;
    int* off = (blockIdx.x == 0) ? g_OFFS : g_OFFD;
    int* cur = (blockIdx.x == 0) ? g_CURS : g_CURD;
    int t = threadIdx.x, w = t >> 5, l = t & 31;
    int base = t * 20;
    int loc[20];
    int s = 0;
    #pragma unroll
    for (int i = 0; i < 20; i++) {
        int idx = base + i;
        int c = (idx < NN) ? cnt[idx] : 0;
        loc[i] = s; s += c;
    }
    int incl = s;
    #pragma unroll
    for (int o = 1; o < 32; o <<= 1) {
        int v = __shfl_up_sync(0xffffffffu, incl, o);
        if (l >= o) incl += v;
    }
    if (l == 31) swt[w] = incl;
    __syncthreads();
    if (w == 0) {
        int v = (l < 16) ? swt[l] : 0;
        int iv = v;
        #pragma unroll
        for (int o = 1; o < 16; o <<= 1) {
            int u = __shfl_up_sync(0xffffffffu, iv, o);
            if (l >= o) iv += u;
        }
        if (l < 16) swe[l] = iv - v;
    }
    __syncthreads();
    int excl = incl - s + swe[w];
    #pragma unroll
    for (int i = 0; i < 20; i++) {
        int idx = base + i;
        if (idx < NN) { int o2 = excl + loc[i]; off[idx] = o2; cur[idx] = o2; }
    }
    if (t == 511) off[NN] = excl + s;
}

__global__ void k_bucket(const int* __restrict__ ei) {
    int e = blockIdx.x * 256 + threadIdx.x;
    int src = __ldg(&ei[e]), dst = __ldg(&ei[NE + e]);
    g_SEID[atomicAdd(&g_CURS[src], 1)] = e;
    g_DEID[atomicAdd(&g_CURD[dst], 1)] = e;
}

// per-node: layernorms, s/d projections, QK = q projected through key weights
__global__ void k_node(const float* __restrict__ node,
                       const float* __restrict__ g0, const float* __restrict__ g1,
                       const float* __restrict__ Wq0, const float* __restrict__ Wq1,
                       const float* __restrict__ Ws0, const float* __restrict__ Ws1,
                       const float* __restrict__ Wd0, const float* __restrict__ Wd1,
                       const float* __restrict__ Wkv0, const float* __restrict__ Wkv1) {
    extern __shared__ float sm[];
    float* sW0T = sm;                 // [col<256][c<48]
    float* sW1T = sm + 12288;         // [col<128][u<64]
    int warp = threadIdx.x >> 5, lane = threadIdx.x & 31;
    float* wb  = sm + 12288 + 8192 + warp * 800;
    float* h0s = wb;
    float* h1s = wb + 64;
    float* q0s = wb + 160;
    float* q1s = wb + 416;

    for (int i = threadIdx.x; i < 48*256; i += 256) {
        int c = i >> 8, col = i & 255;
        sW0T[col*48 + c] = Wkv0[c*512 + col];
    }
    for (int i = threadIdx.x; i < 64*128; i += 256) {
        int u = i >> 7, col = i & 127;
        sW1T[col*64 + u] = Wkv1[u*256 + col];
    }
    __syncthreads();

    int n = blockIdx.x * 8 + warp;
    const float* nr = node + (size_t)n * 160;

    float e0 = nr[lane], e1 = nr[32 + lane];
    float mu = warp_sum(e0 + e1) * (1.0f/64.0f);
    float var = warp_sum((e0-mu)*(e0-mu) + (e1-mu)*(e1-mu)) * (1.0f/64.0f);
    float rs0 = rsqrtf(var + EPSLN);
    h0s[lane]    = (e0-mu)*rs0*__ldg(&g0[lane]);
    h0s[32+lane] = (e1-mu)*rs0*__ldg(&g0[32+lane]);
    float t0 = nr[64+lane], t1 = nr[96+lane], t2 = nr[128+lane];
    float vn = warp_sum(t0*t0 + t1*t1 + t2*t2) * (1.0f/32.0f);
    float rs1 = rsqrtf(vn + EPSLN);
    h1s[lane]    = t0*rs1*__ldg(&g1[lane/3]);
    h1s[32+lane] = t1*rs1*__ldg(&g1[(32+lane)/3]);
    h1s[64+lane] = t2*rs1*__ldg(&g1[(64+lane)/3]);
    __syncwarp();

    {
        float a = 0.f, b = 0.f;
        #pragma unroll
        for (int i = 0; i < 64; i++) {
            float h = h0s[i];
            a = fmaf(h, __ldg(&Ws0[i*32 + lane]), a);
            b = fmaf(h, __ldg(&Wd0[i*32 + lane]), b);
        }
        g_SD[(size_t)n*160 + lane]      = a * 0.125f;
        g_SD[(size_t)n*160 + 80 + lane] = b * 0.125f;
    }
    #pragma unroll
    for (int rep = 0; rep < 2; rep++) {
        int j = rep*32 + lane;
        if (j < 48) {
            int v_ = j/3, c_ = j%3;
            float a = 0.f, b = 0.f;
            #pragma unroll
            for (int u = 0; u < 32; u++) {
                float h = h1s[u*3 + c_];
                a = fmaf(h, __ldg(&Ws1[u*16 + v_]), a);
                b = fmaf(h, __ldg(&Wd1[u*16 + v_]), b);
            }
            g_SD[(size_t)n*160 + 32 + j]  = a * INV_SQRT32;
            g_SD[(size_t)n*160 + 112 + j] = b * INV_SQRT32;
        }
    }
    #pragma unroll
    for (int h = 0; h < 8; h++) {
        float a = 0.f;
        #pragma unroll
        for (int i = 0; i < 64; i++) a = fmaf(h0s[i], __ldg(&Wq0[i*256 + h*32 + lane]), a);
        q0s[h*32 + lane] = a * 0.125f;
    }
    #pragma unroll
    for (int k = 0; k < 12; k++) {
        int j = k*32 + lane;
        int h = j/48, r = j%48, v_ = r/3, c_ = r%3;
        float a = 0.f;
        #pragma unroll
        for (int u = 0; u < 32; u++) a = fmaf(h1s[u*3 + c_], __ldg(&Wq1[u*128 + h*16 + v_]), a);
        q1s[j] = a * INV_SQRT32;
    }
    __syncwarp();

    float* qkn = g_QK + (size_t)n * (HH*CPD);
    #pragma unroll
    for (int k = 0; k < 12; k++) {  // qk0: cp index c<48, store [c*8+h]
        int j = k*32 + lane;
        int h = j/48, c = j%48;
        float a = 0.f;
        #pragma unroll
        for (int m = 0; m < 32; m++) a = fmaf(q0s[h*32 + m], sW0T[(h*32+m)*48 + c], a);
        qkn[c*8 + h] = a * F_QK0;
    }
    #pragma unroll
    for (int k = 0; k < 48; k++) {  // qk1: cp index 48+cart*64+u, store [j*8+h]
        int j = k*32 + lane;
        int h = j/192, cart = (j/64)%3, u = j%64;
        float a = 0.f;
        #pragma unroll
        for (int v_ = 0; v_ < 16; v_++)
            a = fmaf(q1s[h*48 + v_*3 + cart], sW1T[(h*16+v_)*64 + u], a);
        qkn[(48 + cart*64 + u)*8 + h] = a * F_QK1;
    }
}

// build 240-dim tensor-product vector for one edge (warp-cooperative)
__device__ __forceinline__ void build_cp(int e, int src, int dst,
                                         const float* __restrict__ rbf,
                                         const float* __restrict__ rsh,
                                         const float* __restrict__ Ws,
                                         float* wb, float* CP, int lane) {
    float* rb  = wb;
    float* ys  = wb + 16;
    float* x0s = wb + 20;
    float* x1s = wb + 52;
    if (lane < 16) rb[lane] = __ldg(&rbf[(size_t)e*16 + lane]);
    if (lane < 4)  ys[lane] = __ldg(&rsh[(size_t)e*4 + lane]);
    x0s[lane] = __ldg(&g_SD[(size_t)src*160 + lane]) + __ldg(&g_SD[(size_t)dst*160 + 80 + lane]);
    x1s[lane] = __ldg(&g_SD[(size_t)src*160 + 32 + lane]) + __ldg(&g_SD[(size_t)dst*160 + 112 + lane]);
    if (lane < 16)
        x1s[32+lane] = __ldg(&g_SD[(size_t)src*160 + 64 + lane]) + __ldg(&g_SD[(size_t)dst*160 + 144 + lane]);
    __syncwarp();

    float y0 = ys[0], y1x = ys[1], y1y = ys[2], y1z = ys[3];
    #define WCH(J, OUT) { float _a = 0.f; _Pragma("unroll") \
        for (int _k = 0; _k < 16; _k++) _a = fmaf(rb[_k], Ws[_k*112 + (J)], _a); OUT = _a; }

    { float w; WCH(lane, w); CP[lane] = w * x0s[lane] * y0; }
    if (lane < 16) {
        float w; WCH(32 + lane, w);
        float d = x1s[lane*3]*y1x + x1s[lane*3+1]*y1y + x1s[lane*3+2]*y1z;
        CP[32 + lane] = w * d * INV_SQRT3;
    }
    { float w; WCH(48 + lane, w);
      float xv = w * x0s[lane];
      CP[48 + lane]       = xv * y1x;
      CP[48 + 64 + lane]  = xv * y1y;
      CP[48 + 128 + lane] = xv * y1z; }
    if (lane < 16) {
        float w; WCH(80 + lane, w);
        float wy = w * y0;
        CP[48 + 32 + lane]       = wy * x1s[lane*3];
        CP[48 + 64 + 32 + lane]  = wy * x1s[lane*3+1];
        CP[48 + 128 + 32 + lane] = wy * x1s[lane*3+2];
    } else {
        int t = lane - 16;
        float w; WCH(96 + t, w);
        w *= INV_SQRT2;
        float ax = x1s[t*3], ay = x1s[t*3+1], az = x1s[t*3+2];
        CP[48 + 48 + t]       = w * (ay*y1z - az*y1y);
        CP[48 + 64 + 48 + t]  = w * (az*y1x - ax*y1z);
        CP[48 + 128 + 48 + t] = w * (ax*y1y - ay*y1x);
    }
    #undef WCH
    __syncwarp();
}

// per-edge (src-sorted order): build+store CP, logits via L1-resident QK[src]
__global__ void k_edge(const float* __restrict__ rbf, const float* __restrict__ rsh,
                       const int* __restrict__ ei, const float* __restrict__ Wrbf) {
    __shared__ float sW[16*112];
    __shared__ __align__(16) float wbuf[8][352];
    int warp = threadIdx.x >> 5, lane = threadIdx.x & 31;
    for (int i = threadIdx.x; i < 16*112; i += 256) sW[i] = Wrbf[i];
    __syncthreads();

    int e = __ldg(&g_SEID[blockIdx.x * 8 + warp]);
    int src = __ldg(&ei[e]), dst = __ldg(&ei[NE + e]);
    float* wb = wbuf[warp];
    float* CP = wb + 112;
    build_cp(e, src, dst, rbf, rsh, sW, wb, CP, lane);

    float4* dcp = (float4*)(g_CP + (size_t)e*256);
    const float4* scp = (const float4*)CP;
    dcp[lane] = scp[lane];
    if (lane < 28) dcp[32+lane] = scp[32+lane];

    float acc[8] = {0,0,0,0,0,0,0,0};
    const float* qkb = g_QK + (size_t)src * 1920;
    for (int j = lane; j < 240; j += 32) {
        float cp = CP[j];
        const float4* p = (const float4*)(qkb + j*8);
        float4 qa = __ldg(p), qb = __ldg(p + 1);
        acc[0] = fmaf(cp, qa.x, acc[0]); acc[1] = fmaf(cp, qa.y, acc[1]);
        acc[2] = fmaf(cp, qa.z, acc[2]); acc[3] = fmaf(cp, qa.w, acc[3]);
        acc[4] = fmaf(cp, qb.x, acc[4]); acc[5] = fmaf(cp, qb.y, acc[5]);
        acc[6] = fmaf(cp, qb.z, acc[6]); acc[7] = fmaf(cp, qb.w, acc[7]);
    }
    #pragma unroll
    for (int o = 16; o; o >>= 1)
        #pragma unroll
        for (int h = 0; h < 8; h++) acc[h] += __shfl_xor_sync(0xffffffffu, acc[h], o);
    if (lane < 8) g_LG[(size_t)e*8 + lane] = acc[lane];
}

// per-node: softmax over in-edges, accumulate attn-weighted CP, value GEMM
__global__ void k_gather(const float* __restrict__ Wkv0, const float* __restrict__ Wkv1) {
    extern __shared__ float sg[];
    float* sWv0 = sg;             // [c<48][j<256]
    float* sWv1 = sg + 12288;     // [u<64][j<128]
    float* sACP = sg + 20480;     // 8 warps x 2048
    float* sMZ  = sg + 36864;     // 8 warps x 16

    int warp = threadIdx.x >> 5, lane = threadIdx.x & 31;
    for (int i = threadIdx.x; i < 12288; i += 256) {
        int c = i >> 8, j = i & 255;
        sWv0[i] = Wkv0[c*512 + 256 + j];
    }
    for (int i = threadIdx.x; i < 8192; i += 256) {
        int u = i >> 7, j = i & 127;
        sWv1[i] = Wkv1[u*256 + 128 + j];
    }
    __syncthreads();

    int n = blockIdx.x * 8 + warp;
    int start = g_OFFD[n];
    int deg = g_OFFD[n+1] - start;

    int q = lane >> 3, h = lane & 7;
    float m = -INFINITY;
    for (int i = q; i < deg; i += 4) {
        int e = g_DEID[start + i];
        m = fmaxf(m, __ldg(&g_LG[(size_t)e*8 + h]));
    }
    m = fmaxf(m, __shfl_xor_sync(0xffffffffu, m, 8));
    m = fmaxf(m, __shfl_xor_sync(0xffffffffu, m, 16));
    float z = 0.f;
    for (int i = q; i < deg; i += 4) {
        int e = g_DEID[start + i];
        z += __expf(__ldg(&g_LG[(size_t)e*8 + h]) - m);
    }
    z += __shfl_xor_sync(0xffffffffu, z, 8);
    z += __shfl_xor_sync(0xffffffffu, z, 16);
    float* mz = sMZ + warp*16;
    if (lane < 8) { mz[lane] = m; mz[8 + lane] = 1.f / (z + 1e-16f); }
    __syncwarp();

    float4 aA[8], aB[8];
    #pragma unroll
    for (int hh = 0; hh < 8; hh++) { aA[hh] = make_float4(0,0,0,0); aB[hh] = make_float4(0,0,0,0); }
    for (int i = 0; i < deg; i += 2) {
        int e0 = g_DEID[start + i];
        bool has1 = (i + 1 < deg);
        int e1 = has1 ? g_DEID[start + i + 1] : e0;
        float att0 = 0.f, att1 = 0.f;
        if (lane < 8) {
            att0 = __expf(__ldg(&g_LG[(size_t)e0*8 + lane]) - mz[lane]) * mz[8 + lane];
            if (has1) att1 = __expf(__ldg(&g_LG[(size_t)e1*8 + lane]) - mz[lane]) * mz[8 + lane];
        }
        const float4* cp0 = (const float4*)(g_CP + (size_t)e0*256);
        const float4* cp1 = (const float4*)(g_CP + (size_t)e1*256);
        float4 c0a = __ldg(&cp0[lane]);
        float4 c1a = __ldg(&cp1[lane]);
        float4 c0b, c1b;
        if (lane < 28) { c0b = __ldg(&cp0[32 + lane]); c1b = __ldg(&cp1[32 + lane]); }
        else { c0b = make_float4(0,0,0,0); c1b = make_float4(0,0,0,0); }
        #pragma unroll
        for (int hh = 0; hh < 8; hh++) {
            float a0 = __shfl_sync(0xffffffffu, att0, hh);
            float a1 = __shfl_sync(0xffffffffu, att1, hh);
            fma4(aA[hh], a0, c0a);
            fma4(aB[hh], a0, c0b);
            fma4(aA[hh], a1, c1a);
            fma4(aB[hh], a1, c1b);
        }
    }
    float* sa = sACP + warp*2048;
    #pragma unroll
    for (int hh = 0; hh < 8; hh++) {
        ((float4*)sa)[hh*64 + lane] = aA[hh];
        ((float4*)sa)[hh*64 + 32 + lane] = aB[hh];
    }
    __syncwarp();

    float acc0[8] = {0,0,0,0,0,0,0,0};
    for (int c = 0; c < 48; c += 4) {
        #pragma unroll
        for (int hh = 0; hh < 8; hh++) {
            float4 a4 = *(const float4*)(sa + hh*256 + c);
            float r = acc0[hh];
            r = fmaf(a4.x, sWv0[(c+0)*256 + hh*32 + lane], r);
            r = fmaf(a4.y, sWv0[(c+1)*256 + hh*32 + lane], r);
            r = fmaf(a4.z, sWv0[(c+2)*256 + hh*32 + lane], r);
            r = fmaf(a4.w, sWv0[(c+3)*256 + hh*32 + lane], r);
            acc0[hh] = r;
        }
    }
    float* mrow = g_MSG + (size_t)n * 640;
    #pragma unroll
    for (int hh = 0; hh < 8; hh++) mrow[hh*80 + lane] = acc0[hh] * INV_SQRT48;

    float acc1[4][3];
    #pragma unroll
    for (int k = 0; k < 4; k++)
        #pragma unroll
        for (int c = 0; c < 3; c++) acc1[k][c] = 0.f;
    for (int u = 0; u < 64; u += 4) {
        #pragma unroll
        for (int k = 0; k < 4; k++) {
            int jj = lane + 32*k;
            int hb = jj >> 4;
            const float* ap = sa + hb*256 + 48 + u;
            float4 ax = *(const float4*)(ap);
            float4 ay = *(const float4*)(ap + 64);
            float4 az = *(const float4*)(ap + 128);
            float w0 = sWv1[(u+0)*128 + jj];
            float w1 = sWv1[(u+1)*128 + jj];
            float w2 = sWv1[(u+2)*128 + jj];
            float w3 = sWv1[(u+3)*128 + jj];
            acc1[k][0] = fmaf(ax.x,w0, fmaf(ax.y,w1, fmaf(ax.z,w2, fmaf(ax.w,w3, acc1[k][0]))));
            acc1[k][1] = fmaf(ay.x,w0, fmaf(ay.y,w1, fmaf(ay.z,w2, fmaf(ay.w,w3, acc1[k][1]))));
            acc1[k][2] = fmaf(az.x,w0, fmaf(az.y,w1, fmaf(az.z,w2, fmaf(az.w,w3, acc1[k][2]))));
        }
    }
    #pragma unroll
    for (int k = 0; k < 4; k++) {
        int jj = lane + 32*k;
        int hb = jj >> 4, v_ = jj & 15;
        #pragma unroll
        for (int c = 0; c < 3; c++)
            mrow[hb*80 + 32 + v_*3 + c] = acc1[k][c] * 0.125f;
    }
}

__global__ void k_out(const float* __restrict__ node,
                      const float* __restrict__ Wm0, const float* __restrict__ Wm1,
                      float* __restrict__ out) {
    __shared__ float msgs_all[8][640];
    int warp = threadIdx.x >> 5, lane = threadIdx.x & 31;
    int n = blockIdx.x * 8 + warp;
    float* msgs = msgs_all[warp];
    for (int j = lane; j < 640; j += 32) msgs[j] = g_MSG[(size_t)n*640 + j];
    __syncwarp();

    const float* nr = node + (size_t)n * 160;
    float* orow = out + (size_t)n * 160;

    float a0 = 0.f, a1 = 0.f;
    #pragma unroll 8
    for (int i = 0; i < 256; i++) {
        float m = msgs[(i >> 5)*80 + (i & 31)];
        a0 = fmaf(m, __ldg(&Wm0[i*64 + lane]), a0);
        a1 = fmaf(m, __ldg(&Wm0[i*64 + 32 + lane]), a1);
    }
    orow[lane]      = nr[lane]      + a0 * INV16;
    orow[32 + lane] = nr[32 + lane] + a1 * INV16;

    float c0 = 0.f, c1 = 0.f, c2 = 0.f;
    #pragma unroll 8
    for (int u = 0; u < 128; u++) {
        int hh = u >> 4, v_ = u & 15;
        float w = __ldg(&Wm1[u*32 + lane]);
        const float* mp = msgs + hh*80 + 32 + v_*3;
        c0 = fmaf(mp[0], w, c0);
        c1 = fmaf(mp[1], w, c1);
        c2 = fmaf(mp[2], w, c2);
    }
    orow[64 + lane*3 + 0] = nr[64 + lane*3 + 0] + c0 * INV_SQRT128;
    orow[64 + lane*3 + 1] = nr[64 + lane*3 + 1] + c1 * INV_SQRT128;
    orow[64 + lane*3 + 2] = nr[64 + lane*3 + 2] + c2 * INV_SQRT128;
}

extern "C" void kernel_launch(void* const* d_in, const int* in_sizes, int n_in,
                              void* d_out, int out_size) {
    const float* node = (const float*)d_in[0];
    const float* rbf  = (const float*)d_in[1];
    const float* rsh  = (const float*)d_in[2];
    const int*   ei   = (const int*)d_in[3];
    const float* g0   = (const float*)d_in[4];
    const float* g1   = (const float*)d_in[5];
    const float* Wq0  = (const float*)d_in[6];
    const float* Wq1  = (const float*)d_in[7];
    const float* Ws0  = (const float*)d_in[8];
    const float* Ws1  = (const float*)d_in[9];
    const float* Wd0  = (const float*)d_in[10];
    const float* Wd1  = (const float*)d_in[11];
    const float* Wrbf = (const float*)d_in[12];
    const float* Wkv0 = (const float*)d_in[13];
    const float* Wkv1 = (const float*)d_in[14];
    const float* Wm0  = (const float*)d_in[15];
    const float* Wm1  = (const float*)d_in[16];
    float* out = (float*)d_out;

    cudaFuncSetAttribute(k_node, cudaFuncAttributeMaxDynamicSharedMemorySize, 107520);
    cudaFuncSetAttribute(k_gather, cudaFuncAttributeMaxDynamicSharedMemorySize, 147968);

    k_init<<<40, 256>>>();
    k_hist<<<NE/256, 256>>>(ei);
    k_scan<<<2, 512>>>();
    k_bucket<<<NE/256, 256>>>(ei);
    k_node<<<NN/8, 256, 107520>>>(node, g0, g1, Wq0, Wq1, Ws0, Ws1, Wd0, Wd1, Wkv0, Wkv1);
    k_edge<<<NE/8, 256>>>(rbf, rsh, ei, Wrbf);
    k_gather<<<NN/8, 256, 147968>>>(Wkv0, Wkv1);
    k_out<<<NN/8, 256>>>(node, Wm0, Wm1, out);
}

// round 6
// speedup vs baseline: 1.3879x; 1.0810x over previous
#include <cuda_runtime.h>
#include <math.h>
#include <stdint.h>

#define NN 10000
#define NE 160000
#define HH 8
#define CPD 240
#define EPSLN 1e-5f
#define INV_SQRT2  0.70710678118654752f
#define INV_SQRT3  0.57735026918962576f
#define INV_SQRT32 0.17677669529663689f
#define INV_SQRT48 0.14433756729740643f
#define F_QK0 (1.0f/48.0f)
#define F_QK1 0.018042195912175804f
#define INV16 0.0625f
#define INV_SQRT128 0.08838834764831845f
#define GRID_CSR 296

__device__ float g_SD[NN*160];
__device__ __align__(16) float g_QK[(size_t)NN*HH*CPD];   // [n][j<240][h<8]
__device__ __align__(16) float g_CP[(size_t)NE*256];      // dst-slot order
__device__ float g_LG[(size_t)NE*8];                      // dst-slot order
__device__ int   g_CNTS[NN], g_CNTD[NN];
__device__ int   g_OFFS[NN+1], g_OFFD[NN+1];
__device__ int   g_CURS[NN], g_CURD[NN];
__device__ int   g_SEID[NE];    // src-sorted edge ids
__device__ int   g_POS[NE];     // dst-CSR slot per edge
__device__ __align__(16) float g_MSG[NN*640];
__device__ int   g_barA, g_barB, g_barC, g_barD;

__device__ __forceinline__ float warp_sum(float v) {
    #pragma unroll
    for (int o = 16; o; o >>= 1) v += __shfl_xor_sync(0xffffffffu, v, o);
    return v;
}
__device__ __forceinline__ void fma4(float4& a, float s, const float4 w) {
    a.x = fmaf(s, w.x, a.x); a.y = fmaf(s, w.y, a.y);
    a.z = fmaf(s, w.z, a.z); a.w = fmaf(s, w.w, a.w);
}
__device__ __forceinline__ void grid_bar(int* bar, int target) {
    __syncthreads();
    if (threadIdx.x == 0) {
        __threadfence();
        atomicAdd(bar, 1);
        while (*(volatile int*)bar < target) { }
    }
    __syncthreads();
    __threadfence();
}

// fused: zero counters -> histogram -> dual exclusive scan -> bucket
__global__ void k_csr(const int* __restrict__ ei) {
    int tid = threadIdx.x;
    int gtid = blockIdx.x * 256 + tid;

    for (int i = gtid; i < NN; i += GRID_CSR*256) { g_CNTS[i] = 0; g_CNTD[i] = 0; }
    grid_bar(&g_barA, GRID_CSR);

    for (int e = gtid; e < NE; e += GRID_CSR*256) {
        atomicAdd(&g_CNTS[__ldg(&ei[e])], 1);
        atomicAdd(&g_CNTD[__ldg(&ei[NE + e])], 1);
    }
    grid_bar(&g_barB, GRID_CSR);

    if (blockIdx.x < 2) {
        const int* cnt = (blockIdx.x == 0) ? g_CNTS : g_CNTD;
        int* off = (blockIdx.x == 0) ? g_OFFS : g_OFFD;
        int* cur = (blockIdx.x == 0) ? g_CURS : g_CURD;
        __shared__ int swt[8], swe[8];
        int w = tid >> 5, l = tid & 31;
        int base = tid * 40;
        int loc[40];
        int s = 0;
        #pragma unroll
        for (int i = 0; i < 40; i++) {
            int idx = base + i;
            int c = (idx < NN) ? cnt[idx] : 0;
            loc[i] = s; s += c;
        }
        int incl = s;
        #pragma unroll
        for (int o = 1; o < 32; o <<= 1) {
            int v = __shfl_up_sync(0xffffffffu, incl, o);
            if (l >= o) incl += v;
        }
        if (l == 31) swt[w] = incl;
        __syncthreads();
        if (w == 0) {
            int v = (l < 8) ? swt[l] : 0;
            int iv = v;
            #pragma unroll
            for (int o = 1; o < 8; o <<= 1) {
                int u = __shfl_up_sync(0xffffffffu, iv, o);
                if (l >= o) iv += u;
            }
            if (l < 8) swe[l] = iv - v;
        }
        __syncthreads();
        int excl = incl - s + swe[w];
        #pragma unroll
        for (int i = 0; i < 40; i++) {
            int idx = base + i;
            if (idx < NN) { int o2 = excl + loc[i]; off[idx] = o2; cur[idx] = o2; }
        }
        if (tid == 255) off[NN] = excl + s;
    }
    grid_bar(&g_barC, GRID_CSR);

    for (int e = gtid; e < NE; e += GRID_CSR*256) {
        int src = __ldg(&ei[e]), dst = __ldg(&ei[NE + e]);
        g_SEID[atomicAdd(&g_CURS[src], 1)] = e;
        g_POS[e] = atomicAdd(&g_CURD[dst], 1);
    }
    __syncthreads();
    if (tid == 0) {
        __threadfence();
        int old = atomicAdd(&g_barD, 1);
        if (old == GRID_CSR - 1) { g_barA = 0; g_barB = 0; g_barC = 0; g_barD = 0; }
    }
}

// per-node: layernorms, s/d projections, QK = q projected through key weights
__global__ void k_node(const float* __restrict__ node,
                       const float* __restrict__ g0, const float* __restrict__ g1,
                       const float* __restrict__ Wq0, const float* __restrict__ Wq1,
                       const float* __restrict__ Ws0, const float* __restrict__ Ws1,
                       const float* __restrict__ Wd0, const float* __restrict__ Wd1,
                       const float* __restrict__ Wkv0, const float* __restrict__ Wkv1) {
    extern __shared__ float sm[];
    float* sW0T = sm;                 // [col<256][c<48]
    float* sW1T = sm + 12288;         // [col<128][u<64]
    int warp = threadIdx.x >> 5, lane = threadIdx.x & 31;
    float* wb  = sm + 12288 + 8192 + warp * 800;
    float* h0s = wb;
    float* h1s = wb + 64;
    float* q0s = wb + 160;
    float* q1s = wb + 416;

    for (int i = threadIdx.x; i < 48*256; i += 256) {
        int c = i >> 8, col = i & 255;
        sW0T[col*48 + c] = Wkv0[c*512 + col];
    }
    for (int i = threadIdx.x; i < 64*128; i += 256) {
        int u = i >> 7, col = i & 127;
        sW1T[col*64 + u] = Wkv1[u*256 + col];
    }
    __syncthreads();

    int n = blockIdx.x * 8 + warp;
    const float* nr = node + (size_t)n * 160;

    float e0 = nr[lane], e1 = nr[32 + lane];
    float mu = warp_sum(e0 + e1) * (1.0f/64.0f);
    float var = warp_sum((e0-mu)*(e0-mu) + (e1-mu)*(e1-mu)) * (1.0f/64.0f);
    float rs0 = rsqrtf(var + EPSLN);
    h0s[lane]    = (e0-mu)*rs0*__ldg(&g0[lane]);
    h0s[32+lane] = (e1-mu)*rs0*__ldg(&g0[32+lane]);
    float t0 = nr[64+lane], t1 = nr[96+lane], t2 = nr[128+lane];
    float vn = warp_sum(t0*t0 + t1*t1 + t2*t2) * (1.0f/32.0f);
    float rs1 = rsqrtf(vn + EPSLN);
    h1s[lane]    = t0*rs1*__ldg(&g1[lane/3]);
    h1s[32+lane] = t1*rs1*__ldg(&g1[(32+lane)/3]);
    h1s[64+lane] = t2*rs1*__ldg(&g1[(64+lane)/3]);
    __syncwarp();

    {
        float a = 0.f, b = 0.f;
        #pragma unroll
        for (int i = 0; i < 64; i++) {
            float h = h0s[i];
            a = fmaf(h, __ldg(&Ws0[i*32 + lane]), a);
            b = fmaf(h, __ldg(&Wd0[i*32 + lane]), b);
        }
        g_SD[(size_t)n*160 + lane]      = a * 0.125f;
        g_SD[(size_t)n*160 + 80 + lane] = b * 0.125f;
    }
    #pragma unroll
    for (int rep = 0; rep < 2; rep++) {
        int j = rep*32 + lane;
        if (j < 48) {
            int v_ = j/3, c_ = j%3;
            float a = 0.f, b = 0.f;
            #pragma unroll
            for (int u = 0; u < 32; u++) {
                float h = h1s[u*3 + c_];
                a = fmaf(h, __ldg(&Ws1[u*16 + v_]), a);
                b = fmaf(h, __ldg(&Wd1[u*16 + v_]), b);
            }
            g_SD[(size_t)n*160 + 32 + j]  = a * INV_SQRT32;
            g_SD[(size_t)n*160 + 112 + j] = b * INV_SQRT32;
        }
    }
    #pragma unroll
    for (int h = 0; h < 8; h++) {
        float a = 0.f;
        #pragma unroll
        for (int i = 0; i < 64; i++) a = fmaf(h0s[i], __ldg(&Wq0[i*256 + h*32 + lane]), a);
        q0s[h*32 + lane] = a * 0.125f;
    }
    #pragma unroll
    for (int k = 0; k < 12; k++) {
        int j = k*32 + lane;
        int h = j/48, r = j%48, v_ = r/3, c_ = r%3;
        float a = 0.f;
        #pragma unroll
        for (int u = 0; u < 32; u++) a = fmaf(h1s[u*3 + c_], __ldg(&Wq1[u*128 + h*16 + v_]), a);
        q1s[j] = a * INV_SQRT32;
    }
    __syncwarp();

    float* qkn = g_QK + (size_t)n * (HH*CPD);
    #pragma unroll
    for (int k = 0; k < 12; k++) {
        int j = k*32 + lane;
        int h = j/48, c = j%48;
        float a = 0.f;
        #pragma unroll
        for (int m = 0; m < 32; m++) a = fmaf(q0s[h*32 + m], sW0T[(h*32+m)*48 + c], a);
        qkn[c*8 + h] = a * F_QK0;
    }
    #pragma unroll
    for (int k = 0; k < 48; k++) {
        int j = k*32 + lane;
        int h = j/192, cart = (j/64)%3, u = j%64;
        float a = 0.f;
        #pragma unroll
        for (int v_ = 0; v_ < 16; v_++)
            a = fmaf(q1s[h*48 + v_*3 + cart], sW1T[(h*16+v_)*64 + u], a);
        qkn[(48 + cart*64 + u)*8 + h] = a * F_QK1;
    }
}

// build 240-dim tensor-product vector for one edge (warp-cooperative)
__device__ __forceinline__ void build_cp(int e, int src, int dst,
                                         const float* __restrict__ rbf,
                                         const float* __restrict__ rsh,
                                         const float* __restrict__ Ws,
                                         float* wb, float* CP, int lane) {
    float* rb  = wb;
    float* ys  = wb + 16;
    float* x0s = wb + 20;
    float* x1s = wb + 52;
    if (lane < 16) rb[lane] = __ldg(&rbf[(size_t)e*16 + lane]);
    if (lane < 4)  ys[lane] = __ldg(&rsh[(size_t)e*4 + lane]);
    x0s[lane] = __ldg(&g_SD[(size_t)src*160 + lane]) + __ldg(&g_SD[(size_t)dst*160 + 80 + lane]);
    x1s[lane] = __ldg(&g_SD[(size_t)src*160 + 32 + lane]) + __ldg(&g_SD[(size_t)dst*160 + 112 + lane]);
    if (lane < 16)
        x1s[32+lane] = __ldg(&g_SD[(size_t)src*160 + 64 + lane]) + __ldg(&g_SD[(size_t)dst*160 + 144 + lane]);
    __syncwarp();

    float y0 = ys[0], y1x = ys[1], y1y = ys[2], y1z = ys[3];
    #define WCH(J, OUT) { float _a = 0.f; _Pragma("unroll") \
        for (int _k = 0; _k < 16; _k++) _a = fmaf(rb[_k], Ws[_k*112 + (J)], _a); OUT = _a; }

    { float w; WCH(lane, w); CP[lane] = w * x0s[lane] * y0; }
    if (lane < 16) {
        float w; WCH(32 + lane, w);
        float d = x1s[lane*3]*y1x + x1s[lane*3+1]*y1y + x1s[lane*3+2]*y1z;
        CP[32 + lane] = w * d * INV_SQRT3;
    }
    { float w; WCH(48 + lane, w);
      float xv = w * x0s[lane];
      CP[48 + lane]       = xv * y1x;
      CP[48 + 64 + lane]  = xv * y1y;
      CP[48 + 128 + lane] = xv * y1z; }
    if (lane < 16) {
        float w; WCH(80 + lane, w);
        float wy = w * y0;
        CP[48 + 32 + lane]       = wy * x1s[lane*3];
        CP[48 + 64 + 32 + lane]  = wy * x1s[lane*3+1];
        CP[48 + 128 + 32 + lane] = wy * x1s[lane*3+2];
    } else {
        int t = lane - 16;
        float w; WCH(96 + t, w);
        w *= INV_SQRT2;
        float ax = x1s[t*3], ay = x1s[t*3+1], az = x1s[t*3+2];
        CP[48 + 48 + t]       = w * (ay*y1z - az*y1y);
        CP[48 + 64 + 48 + t]  = w * (az*y1x - ax*y1z);
        CP[48 + 128 + 48 + t] = w * (ax*y1y - ay*y1x);
    }
    #undef WCH
    __syncwarp();
}

// per-edge (src-sorted): build CP, logits; write CP+LG at dst-CSR slot
__global__ void k_edge(const float* __restrict__ rbf, const float* __restrict__ rsh,
                       const int* __restrict__ ei, const float* __restrict__ Wrbf) {
    __shared__ float sW[16*112];
    __shared__ __align__(16) float wbuf[8][352];
    int warp = threadIdx.x >> 5, lane = threadIdx.x & 31;
    for (int i = threadIdx.x; i < 16*112; i += 256) sW[i] = Wrbf[i];
    __syncthreads();

    int e = __ldg(&g_SEID[blockIdx.x * 8 + warp]);
    int src = __ldg(&ei[e]), dst = __ldg(&ei[NE + e]);
    int slot = __ldg(&g_POS[e]);
    float* wb = wbuf[warp];
    float* CP = wb + 112;
    build_cp(e, src, dst, rbf, rsh, sW, wb, CP, lane);

    float4* dcp = (float4*)(g_CP + (size_t)slot*256);
    const float4* scp = (const float4*)CP;
    dcp[lane] = scp[lane];
    if (lane < 28) dcp[32+lane] = scp[32+lane];

    float acc[8] = {0,0,0,0,0,0,0,0};
    const float* qkb = g_QK + (size_t)src * 1920;
    for (int j = lane; j < 240; j += 32) {
        float cp = CP[j];
        const float4* p = (const float4*)(qkb + j*8);
        float4 qa = __ldg(p), qb = __ldg(p + 1);
        acc[0] = fmaf(cp, qa.x, acc[0]); acc[1] = fmaf(cp, qa.y, acc[1]);
        acc[2] = fmaf(cp, qa.z, acc[2]); acc[3] = fmaf(cp, qa.w, acc[3]);
        acc[4] = fmaf(cp, qb.x, acc[4]); acc[5] = fmaf(cp, qb.y, acc[5]);
        acc[6] = fmaf(cp, qb.z, acc[6]); acc[7] = fmaf(cp, qb.w, acc[7]);
    }
    #pragma unroll
    for (int o = 16; o; o >>= 1)
        #pragma unroll
        for (int h = 0; h < 8; h++) acc[h] += __shfl_xor_sync(0xffffffffu, acc[h], o);
    if (lane < 8) g_LG[(size_t)slot*8 + lane] = acc[lane];
}

// per-node: softmax (streamed logits), accumulate attn-weighted CP (streamed), value GEMM
__global__ void k_gather(const float* __restrict__ Wkv0, const float* __restrict__ Wkv1) {
    extern __shared__ float sg[];
    float* sWv0 = sg;             // [c<48][j<256]
    float* sWv1 = sg + 12288;     // [u<64][j<128]
    float* sST  = sg + 20480;     // 8 warps x 512 (2-head staging)
    float* sMZ  = sg + 24576;     // 8 warps x 16

    int warp = threadIdx.x >> 5, lane = threadIdx.x & 31;
    for (int i = threadIdx.x; i < 12288; i += 256) {
        int c = i >> 8, j = i & 255;
        sWv0[i] = Wkv0[c*512 + 256 + j];
    }
    for (int i = threadIdx.x; i < 8192; i += 256) {
        int u = i >> 7, j = i & 127;
        sWv1[i] = Wkv1[u*256 + 128 + j];
    }
    __syncthreads();

    int n = blockIdx.x * 8 + warp;
    int start = g_OFFD[n];
    int deg = g_OFFD[n+1] - start;

    // pass 1: per-head max and Z over streamed logits
    int q = lane >> 3, h = lane & 7;
    float m = -INFINITY;
    for (int i = q; i < deg; i += 4)
        m = fmaxf(m, __ldg(&g_LG[(size_t)(start+i)*8 + h]));
    m = fmaxf(m, __shfl_xor_sync(0xffffffffu, m, 8));
    m = fmaxf(m, __shfl_xor_sync(0xffffffffu, m, 16));
    float z = 0.f;
    for (int i = q; i < deg; i += 4)
        z += __expf(__ldg(&g_LG[(size_t)(start+i)*8 + h]) - m);
    z += __shfl_xor_sync(0xffffffffu, z, 8);
    z += __shfl_xor_sync(0xffffffffu, z, 16);
    float* mz = sMZ + warp*16;
    if (lane < 8) { mz[lane] = m; mz[8 + lane] = 1.f / (z + 1e-16f); }
    __syncwarp();

    // pass 2: streamed attn-weighted CP accumulation
    float4 aA[8], aB[8];
    #pragma unroll
    for (int hh = 0; hh < 8; hh++) { aA[hh] = make_float4(0,0,0,0); aB[hh] = make_float4(0,0,0,0); }
    for (int i = 0; i < deg; i += 2) {
        int s0 = start + i;
        bool has1 = (i + 1 < deg);
        int s1 = has1 ? s0 + 1 : s0;
        float att0 = 0.f, att1 = 0.f;
        if (lane < 8) {
            att0 = __expf(__ldg(&g_LG[(size_t)s0*8 + lane]) - mz[lane]) * mz[8 + lane];
            if (has1) att1 = __expf(__ldg(&g_LG[(size_t)s1*8 + lane]) - mz[lane]) * mz[8 + lane];
        }
        const float4* cp0 = (const float4*)(g_CP + (size_t)s0*256);
        const float4* cp1 = (const float4*)(g_CP + (size_t)s1*256);
        float4 c0a = __ldg(&cp0[lane]);
        float4 c1a = __ldg(&cp1[lane]);
        float4 c0b, c1b;
        if (lane < 28) { c0b = __ldg(&cp0[32 + lane]); c1b = __ldg(&cp1[32 + lane]); }
        else { c0b = make_float4(0,0,0,0); c1b = make_float4(0,0,0,0); }
        #pragma unroll
        for (int hh = 0; hh < 8; hh++) {
            float a0 = __shfl_sync(0xffffffffu, att0, hh);
            float a1 = __shfl_sync(0xffffffffu, att1, hh);
            fma4(aA[hh], a0, c0a);
            fma4(aB[hh], a0, c0b);
            fma4(aA[hh], a1, c1a);
            fma4(aB[hh], a1, c1b);
        }
    }

    // value GEMM per head-pair via small staging buffer
    float* st = sST + warp*512;
    float* mrow = g_MSG + (size_t)n * 640;
    #pragma unroll
    for (int p = 0; p < 4; p++) {
        int h0 = 2*p, h1 = 2*p + 1;
        ((float4*)st)[lane]      = aA[h0];
        ((float4*)st)[32 + lane] = aB[h0];
        ((float4*)st)[64 + lane] = aA[h1];
        ((float4*)st)[96 + lane] = aB[h1];
        __syncwarp();

        // msg0: output m = lane for heads h0,h1
        float a0 = 0.f, a1 = 0.f;
        #pragma unroll 4
        for (int c = 0; c < 48; c++) {
            a0 = fmaf(st[c],       sWv0[c*256 + h0*32 + lane], a0);
            a1 = fmaf(st[256 + c], sWv0[c*256 + h1*32 + lane], a1);
        }
        mrow[h0*80 + lane] = a0 * INV_SQRT48;
        mrow[h1*80 + lane] = a1 * INV_SQRT48;

        // msg1: lanes 0-15 -> head h0, lanes 16-31 -> head h1, v = lane&15
        int hsel = (lane < 16) ? h0 : h1;
        int v_ = lane & 15;
        const float* stv = st + ((lane < 16) ? 0 : 256) + 48;
        float c0 = 0.f, c1 = 0.f, c2 = 0.f;
        #pragma unroll 4
        for (int u = 0; u < 64; u++) {
            float w = sWv1[u*128 + hsel*16 + v_];
            c0 = fmaf(stv[u],       w, c0);
            c1 = fmaf(stv[64 + u],  w, c1);
            c2 = fmaf(stv[128 + u], w, c2);
        }
        mrow[hsel*80 + 32 + v_*3 + 0] = c0 * 0.125f;
        mrow[hsel*80 + 32 + v_*3 + 1] = c1 * 0.125f;
        mrow[hsel*80 + 32 + v_*3 + 2] = c2 * 0.125f;
        __syncwarp();
    }
}

__global__ void k_out(const float* __restrict__ node,
                      const float* __restrict__ Wm0, const float* __restrict__ Wm1,
                      float* __restrict__ out) {
    __shared__ float msgs_all[8][640];
    int warp = threadIdx.x >> 5, lane = threadIdx.x & 31;
    int n = blockIdx.x * 8 + warp;
    float* msgs = msgs_all[warp];
    for (int j = lane; j < 640; j += 32) msgs[j] = g_MSG[(size_t)n*640 + j];
    __syncwarp();

    const float* nr = node + (size_t)n * 160;
    float* orow = out + (size_t)n * 160;

    float a0 = 0.f, a1 = 0.f;
    #pragma unroll 8
    for (int i = 0; i < 256; i++) {
        float m = msgs[(i >> 5)*80 + (i & 31)];
        a0 = fmaf(m, __ldg(&Wm0[i*64 + lane]), a0);
        a1 = fmaf(m, __ldg(&Wm0[i*64 + 32 + lane]), a1);
    }
    orow[lane]      = nr[lane]      + a0 * INV16;
    orow[32 + lane] = nr[32 + lane] + a1 * INV16;

    float c0 = 0.f, c1 = 0.f, c2 = 0.f;
    #pragma unroll 8
    for (int u = 0; u < 128; u++) {
        int hh = u >> 4, v_ = u & 15;
        float w = __ldg(&Wm1[u*32 + lane]);
        const float* mp = msgs + hh*80 + 32 + v_*3;
        c0 = fmaf(mp[0], w, c0);
        c1 = fmaf(mp[1], w, c1);
        c2 = fmaf(mp[2], w, c2);
    }
    orow[64 + lane*3 + 0] = nr[64 + lane*3 + 0] + c0 * INV_SQRT128;
    orow[64 + lane*3 + 1] = nr[64 + lane*3 + 1] + c1 * INV_SQRT128;
    orow[64 + lane*3 + 2] = nr[64 + lane*3 + 2] + c2 * INV_SQRT128;
}

extern "C" void kernel_launch(void* const* d_in, const int* in_sizes, int n_in,
                              void* d_out, int out_size) {
    const float* node = (const float*)d_in[0];
    const float* rbf  = (const float*)d_in[1];
    const float* rsh  = (const float*)d_in[2];
    const int*   ei   = (const int*)d_in[3];
    const float* g0   = (const float*)d_in[4];
    const float* g1   = (const float*)d_in[5];
    const float* Wq0  = (const float*)d_in[6];
    const float* Wq1  = (const float*)d_in[7];
    const float* Ws0  = (const float*)d_in[8];
    const float* Ws1  = (const float*)d_in[9];
    const float* Wd0  = (const float*)d_in[10];
    const float* Wd1  = (const float*)d_in[11];
    const float* Wrbf = (const float*)d_in[12];
    const float* Wkv0 = (const float*)d_in[13];
    const float* Wkv1 = (const float*)d_in[14];
    const float* Wm0  = (const float*)d_in[15];
    const float* Wm1  = (const float*)d_in[16];
    float* out = (float*)d_out;

    cudaFuncSetAttribute(k_node, cudaFuncAttributeMaxDynamicSharedMemorySize, 107520);
    cudaFuncSetAttribute(k_gather, cudaFuncAttributeMaxDynamicSharedMemorySize, 98816);

    k_csr<<<GRID_CSR, 256>>>(ei);
    k_node<<<NN/8, 256, 107520>>>(node, g0, g1, Wq0, Wq1, Ws0, Ws1, Wd0, Wd1, Wkv0, Wkv1);
    k_edge<<<NE/8, 256>>>(rbf, rsh, ei, Wrbf);
    k_gather<<<NN/8, 256, 98816>>>(Wkv0, Wkv1);
    k_out<<<NN/8, 256>>>(node, Wm0, Wm1, out);
}